// round 5
// baseline (speedup 1.0000x reference)
#include <cuda_runtime.h>

#define TOKS    2048
#define NNODES  1024
#define FEAT    128
#define QUADS   32                 // FEAT/4 float4 lanes per token row
#define NBLK    64
#define CHUNK   32                 // TOKS / NBLK
#define THREADS 512
#define NGRP    16                 // warps per block
#define NPW     (NNODES / NGRP)    // 64 nodes per warp
#define BATCH   8

__device__ __forceinline__ float4 f4add(float4 a, float4 b) {
    return make_float4(a.x + b.x, a.y + b.y, a.z + b.z, a.w + b.w);
}

__global__ __launch_bounds__(THREADS, 1)
void span_encoder_kernel(const int* __restrict__ starts,
                         const int* __restrict__ ends,
                         const float4* __restrict__ embed4,
                         float4* __restrict__ out4)
{
    __shared__ __align__(16) int2   s_span[NNODES];       //  8 KB
    __shared__ __align__(16) float  sdiff[CHUNK][FEAT];   // 16 KB diff array
    __shared__ __align__(16) float  gaccs[NGRP][FEAT];    //  8 KB per-warp acc
    __shared__ __align__(16) float  psum[4][FEAT];        //  2 KB combine lvl1
    __shared__ __align__(16) float  sfull[FEAT];          // combined full sum
    __shared__ __align__(16) float4 sred[NGRP][QUADS];    //  8 KB 2-token sums
    __shared__ __align__(16) float4 ssup[4][QUADS];       //  2 KB 8-token sums

    const int tid  = threadIdx.x;
    const int lane = tid & 31;
    const int g    = tid >> 5;               // warp 0..15
    const int q    = lane;                   // float4 lane in feature row
    const int c0   = blockIdx.x * CHUNK;
    const float4 zero4 = make_float4(0.f, 0.f, 0.f, 0.f);

    // ---- Prefetch spans + zero diff array (one parallel pass) -----------
    s_span[tid]           = make_int2(__ldg(&starts[tid]),
                                      __ldg(&ends[tid]));
    s_span[tid + THREADS] = make_int2(__ldg(&starts[tid + THREADS]),
                                      __ldg(&ends[tid + THREADS]));
    {
        float4* df = (float4*)&sdiff[0][0];
        df[tid]           = zero4;
        df[tid + THREADS] = zero4;
    }
    __syncthreads();

    // ---- Main loop: 64 nodes/warp, register-batched span prefetch -------
    {
        float4 a0 = zero4, a1 = zero4, a2 = zero4, a3 = zero4;
        const int nbase = g * NPW;
        #pragma unroll
        for (int b = 0; b < NPW / BATCH; ++b) {          // 8 batches
            int2 sp[BATCH];
            #pragma unroll
            for (int j = 0; j < BATCH; ++j)              // independent LDS.64s
                sp[j] = s_span[nbase + b * BATCH + j];
            #pragma unroll
            for (int j = 0; j < BATCH; ++j) {
                int n  = nbase + b * BATCH + j;
                int lo = sp[j].x - c0;     if (lo < 0)     lo = 0;
                int hi = sp[j].y - c0 + 1; if (hi > CHUNK) hi = CHUNK;
                if (lo < hi) {                           // warp-uniform
                    float4 v = __ldg(&embed4[n * QUADS + q]);
                    if (lo == 0 && hi == CHUNK) {
                        if      ((j & 3) == 0) a0 = f4add(a0, v);
                        else if ((j & 3) == 1) a1 = f4add(a1, v);
                        else if ((j & 3) == 2) a2 = f4add(a2, v);
                        else                   a3 = f4add(a3, v);
                    } else {
                        float* d = &sdiff[lo][q * 4];
                        atomicAdd(d + 0, v.x);
                        atomicAdd(d + 1, v.y);
                        atomicAdd(d + 2, v.z);
                        atomicAdd(d + 3, v.w);
                        if (hi < CHUNK) {
                            float* d2 = &sdiff[hi][q * 4];
                            atomicAdd(d2 + 0, -v.x);
                            atomicAdd(d2 + 1, -v.y);
                            atomicAdd(d2 + 2, -v.z);
                            atomicAdd(d2 + 3, -v.w);
                        }
                    }
                }
            }
        }
        ((float4*)gaccs[g])[q] = f4add(f4add(a0, a1), f4add(a2, a3));
    }
    __syncthreads();

    // ---- Level 1: 4-group partial sums + 2-token slice sums -------------
    {
        int cg = tid >> 7;                   // 0..3
        int f  = tid & (FEAT - 1);
        float s = gaccs[cg * 4 + 0][f] + gaccs[cg * 4 + 1][f]
                + gaccs[cg * 4 + 2][f] + gaccs[cg * 4 + 3][f];
        psum[cg][f] = s;
        sred[g][q] = f4add(((const float4*)sdiff[2 * g])[q],
                           ((const float4*)sdiff[2 * g + 1])[q]);
    }
    __syncthreads();

    // ---- Level 2: full-cover total + 8-token super sums -----------------
    if (tid < FEAT) {
        sfull[tid] = psum[0][tid] + psum[1][tid] + psum[2][tid] + psum[3][tid];
    } else if (tid < 2 * FEAT) {
        int u = tid - FEAT;
        int a = u >> 5, qq = u & 31;
        ssup[a][qq] = f4add(f4add(sred[4 * a + 0][qq], sred[4 * a + 1][qq]),
                            f4add(sred[4 * a + 2][qq], sred[4 * a + 3][qq]));
    }
    __syncthreads();

    // ---- Scan: warp g owns tokens 2g, 2g+1 ------------------------------
    {
        const int a = g >> 2, b = g & 3;
        float4 acc = ((const float4*)sfull)[q];
        #pragma unroll
        for (int s = 0; s < 3; ++s)
            if (s < a) acc = f4add(acc, ssup[s][q]);
        #pragma unroll
        for (int j = 0; j < 3; ++j)
            if (j < b) acc = f4add(acc, sred[4 * a + j][q]);
        acc = f4add(acc, ((const float4*)sdiff[2 * g])[q]);
        out4[(c0 + 2 * g) * QUADS + q] = acc;
        acc = f4add(acc, ((const float4*)sdiff[2 * g + 1])[q]);
        out4[(c0 + 2 * g + 1) * QUADS + q] = acc;
    }
}

extern "C" void kernel_launch(void* const* d_in, const int* in_sizes, int n_in,
                              void* d_out, int out_size) {
    const int*    starts = (const int*)d_in[0];
    const int*    ends   = (const int*)d_in[1];
    const float4* embed  = (const float4*)d_in[2];
    float4*       out    = (float4*)d_out;
    (void)in_sizes; (void)n_in; (void)out_size;
    span_encoder_kernel<<<NBLK, THREADS>>>(starts, ends, embed, out);
}

// round 6
// speedup vs baseline: 1.3844x; 1.3844x over previous
#include <cuda_runtime.h>

#define TOKS    2048
#define NNODES  1024
#define FEAT    128
#define QUADS   32                 // FEAT/4 float4 lanes per token row
#define NBLK    64
#define CHUNK   32                 // TOKS / NBLK
#define THREADS 1024
#define NGRP    32                 // warps per block

__device__ __forceinline__ float4 f4add(float4 a, float4 b) {
    return make_float4(a.x + b.x, a.y + b.y, a.z + b.z, a.w + b.w);
}

__global__ __launch_bounds__(THREADS, 1)
void span_encoder_kernel(const int* __restrict__ starts,
                         const int* __restrict__ ends,
                         const float4* __restrict__ embed4,
                         float4* __restrict__ out4)
{
    __shared__ int    s_full[NNODES];                    //  4 KB compact full list
    __shared__ int    s_part[NNODES];                    //  4 KB packed partials
    __shared__ int    s_nfull, s_npart;
    __shared__ __align__(16) float  sdiff[CHUNK][FEAT];  // 16 KB diff array
    __shared__ __align__(16) float  gaccs[NGRP][FEAT];   // 16 KB per-warp accums
    __shared__ __align__(16) float  psum[2][FEAT];       //  1 KB combine halves
    __shared__ __align__(16) float4 sred[16][QUADS];     //  8 KB 2-token sums
    __shared__ __align__(16) float4 ssup[4][QUADS];      //  2 KB 8-token sums

    const int tid  = threadIdx.x;
    const int lane = tid & 31;
    const int g    = tid >> 5;               // warp 0..31
    const int q    = lane;                   // float4 lane in feature row
    const int c0   = blockIdx.x * CHUNK;
    const unsigned lt_mask = (1u << lane) - 1u;
    const float4 zero4 = make_float4(0.f, 0.f, 0.f, 0.f);

    if (tid == 0) { s_nfull = 0; s_npart = 0; }
    ((float4*)&sdiff[0][0])[tid] = zero4;    // CHUNK*FEAT/4 == 1024

    // ---- Classify: 1 node per thread, ballot compaction (single round) --
    {
        int s  = __ldg(&starts[tid]);
        int e  = __ldg(&ends[tid]);
        int lo = s - c0;     if (lo < 0)     lo = 0;
        int hi = e - c0 + 1; if (hi > CHUNK) hi = CHUNK;
        bool ov     = (lo < hi);
        bool isFull = ov && (lo == 0) && (hi == CHUNK);
        bool isPart = ov && !isFull;

        unsigned mf = __ballot_sync(0xffffffffu, isFull);
        unsigned mp = __ballot_sync(0xffffffffu, isPart);
        int baseF = 0, baseP = 0;
        if (lane == 0) {
            if (mf) baseF = atomicAdd(&s_nfull, __popc(mf));
            if (mp) baseP = atomicAdd(&s_npart, __popc(mp));
        }
        baseF = __shfl_sync(0xffffffffu, baseF, 0);
        baseP = __shfl_sync(0xffffffffu, baseP, 0);
        if (isFull) s_full[baseF + __popc(mf & lt_mask)] = tid;
        if (isPart) s_part[baseP + __popc(mp & lt_mask)] = (tid << 12) | (lo << 6) | hi;
    }
    __syncthreads();

    const int nfull = s_nfull;
    const int npart = s_npart;

    // ---- Full-cover nodes: uniform load loop, MLP=4, ~5 nodes/warp ------
    {
        float4 a0 = zero4, a1 = zero4, a2 = zero4, a3 = zero4;
        int i = g;
        for (; i + 3 * NGRP < nfull; i += 4 * NGRP) {
            int n0 = s_full[i];
            int n1 = s_full[i +     NGRP];
            int n2 = s_full[i + 2 * NGRP];
            int n3 = s_full[i + 3 * NGRP];
            a0 = f4add(a0, __ldg(&embed4[n0 * QUADS + q]));
            a1 = f4add(a1, __ldg(&embed4[n1 * QUADS + q]));
            a2 = f4add(a2, __ldg(&embed4[n2 * QUADS + q]));
            a3 = f4add(a3, __ldg(&embed4[n3 * QUADS + q]));
        }
        for (; i < nfull; i += NGRP)
            a0 = f4add(a0, __ldg(&embed4[s_full[i] * QUADS + q]));

        // ---- Partial nodes: +/- into local diff array (~1/warp) ---------
        for (int p = g; p < npart; p += NGRP) {
            int pk = s_part[p];
            int n  = pk >> 12;
            int lo = (pk >> 6) & 63;
            int hi = pk & 63;
            float4 v = __ldg(&embed4[n * QUADS + q]);
            float* d = &sdiff[lo][q * 4];
            atomicAdd(d + 0, v.x);
            atomicAdd(d + 1, v.y);
            atomicAdd(d + 2, v.z);
            atomicAdd(d + 3, v.w);
            if (hi < CHUNK) {
                float* d2 = &sdiff[hi][q * 4];
                atomicAdd(d2 + 0, -v.x);
                atomicAdd(d2 + 1, -v.y);
                atomicAdd(d2 + 2, -v.z);
                atomicAdd(d2 + 3, -v.w);
            }
        }
        ((float4*)gaccs[g])[q] = f4add(f4add(a0, a1), f4add(a2, a3));
    }
    __syncthreads();

    // ---- One parallel phase: 2-token sums, 8-token sums, accum halves ---
    if (g < 16) {
        sred[g][q] = f4add(((const float4*)sdiff[2 * g])[q],
                           ((const float4*)sdiff[2 * g + 1])[q]);
    } else if (g < 20) {
        int a = g - 16;
        float4 s0 = f4add(((const float4*)sdiff[8 * a + 0])[q],
                          ((const float4*)sdiff[8 * a + 1])[q]);
        float4 s1 = f4add(((const float4*)sdiff[8 * a + 2])[q],
                          ((const float4*)sdiff[8 * a + 3])[q]);
        float4 s2 = f4add(((const float4*)sdiff[8 * a + 4])[q],
                          ((const float4*)sdiff[8 * a + 5])[q]);
        float4 s3 = f4add(((const float4*)sdiff[8 * a + 6])[q],
                          ((const float4*)sdiff[8 * a + 7])[q]);
        ssup[a][q] = f4add(f4add(s0, s1), f4add(s2, s3));
    } else if (g < 28) {
        int u = tid - 20 * 32;               // 0..255
        int h = u >> 7;                      // half 0/1
        int f = u & (FEAT - 1);
        float s = 0.f;
        #pragma unroll
        for (int gg = 0; gg < 16; ++gg) s += gaccs[16 * h + gg][f];
        psum[h][f] = s;
    }
    __syncthreads();

    // ---- Scan: warp g owns token c0+g -----------------------------------
    {
        const int a = g >> 3;
        const int b = (g >> 1) & 3;
        const int k = g & 1;
        float4 acc = f4add(((const float4*)psum[0])[q],
                           ((const float4*)psum[1])[q]);
        #pragma unroll
        for (int s = 0; s < 3; ++s)
            if (s < a) acc = f4add(acc, ssup[s][q]);
        #pragma unroll
        for (int j = 0; j < 3; ++j)
            if (j < b) acc = f4add(acc, sred[4 * a + j][q]);
        if (k) acc = f4add(acc, ((const float4*)sdiff[g - 1])[q]);
        acc = f4add(acc, ((const float4*)sdiff[g])[q]);
        out4[(c0 + g) * QUADS + q] = acc;
    }
}

extern "C" void kernel_launch(void* const* d_in, const int* in_sizes, int n_in,
                              void* d_out, int out_size) {
    const int*    starts = (const int*)d_in[0];
    const int*    ends   = (const int*)d_in[1];
    const float4* embed  = (const float4*)d_in[2];
    float4*       out    = (float4*)d_out;
    (void)in_sizes; (void)n_in; (void)out_size;
    span_encoder_kernel<<<NBLK, THREADS>>>(starts, ends, embed, out);
}